// round 1
// baseline (speedup 1.0000x reference)
#include <cuda_runtime.h>
#include <cuda_bf16.h>

// Problem constants
#define B_   4
#define S_   2048
#define H_   16
#define D_   64
#define HID  1024
#define M_   (B_ * S_)   // 8192

// Scratch for Q,K,V in head layout [B,H,S,Dh]  (allowed: __device__ globals)
__device__ float g_Q[B_ * H_ * S_ * D_];
__device__ float g_K[B_ * H_ * S_ * D_];
__device__ float g_V[B_ * H_ * S_ * D_];

// ---------------------------------------------------------------------------
// Kernel A: SGEMM  out_head = X @ W + bias, written to [B,H,S,Dh] layout.
// 128x128 block tile, BK=8, 256 threads, 8x8 per-thread micro tile.
// ---------------------------------------------------------------------------
__global__ __launch_bounds__(256) void qkv_gemm(const float* __restrict__ X,
                                                const float* __restrict__ W,
                                                const float* __restrict__ bias,
                                                float* __restrict__ outh)
{
    __shared__ float As[8][128];   // As[k][m]  (A stored transposed)
    __shared__ float Bs[8][128];   // Bs[k][n]

    const int tid = threadIdx.x;
    const int ty  = tid >> 4;      // 0..15
    const int tx  = tid & 15;      // 0..15
    const int m0  = blockIdx.y * 128;
    const int n0  = blockIdx.x * 128;

    // A-load mapping: 128 rows x 8 cols, float4 per thread-pair per row
    const int a_row = tid >> 1;          // 0..127
    const int a_col = (tid & 1) * 4;     // 0 or 4
    // B-load mapping: 8 rows x 128 cols, fully coalesced float4
    const int b_row = tid >> 5;          // 0..7
    const int b_col = (tid & 31) * 4;    // 0..124

    float acc[8][8];
    #pragma unroll
    for (int i = 0; i < 8; ++i)
        #pragma unroll
        for (int j = 0; j < 8; ++j) acc[i][j] = 0.f;

    for (int k0 = 0; k0 < HID; k0 += 8) {
        float4 av = *reinterpret_cast<const float4*>(&X[(size_t)(m0 + a_row) * HID + k0 + a_col]);
        As[a_col + 0][a_row] = av.x;
        As[a_col + 1][a_row] = av.y;
        As[a_col + 2][a_row] = av.z;
        As[a_col + 3][a_row] = av.w;
        *reinterpret_cast<float4*>(&Bs[b_row][b_col]) =
            *reinterpret_cast<const float4*>(&W[(size_t)(k0 + b_row) * HID + n0 + b_col]);
        __syncthreads();

        #pragma unroll
        for (int k = 0; k < 8; ++k) {
            float ra[8], rb[8];
            *reinterpret_cast<float4*>(&ra[0]) = *reinterpret_cast<const float4*>(&As[k][ty * 8]);
            *reinterpret_cast<float4*>(&ra[4]) = *reinterpret_cast<const float4*>(&As[k][ty * 8 + 4]);
            *reinterpret_cast<float4*>(&rb[0]) = *reinterpret_cast<const float4*>(&Bs[k][tx * 8]);
            *reinterpret_cast<float4*>(&rb[4]) = *reinterpret_cast<const float4*>(&Bs[k][tx * 8 + 4]);
            #pragma unroll
            for (int i = 0; i < 8; ++i)
                #pragma unroll
                for (int j = 0; j < 8; ++j)
                    acc[i][j] += ra[i] * rb[j];
        }
        __syncthreads();
    }

    // Epilogue: bias add + scatter into [B,H,S,Dh]
    #pragma unroll
    for (int i = 0; i < 8; ++i) {
        const int m = m0 + ty * 8 + i;
        const int b = m >> 11;          // m / 2048
        const int s = m & 2047;
        #pragma unroll
        for (int j = 0; j < 8; ++j) {
            const int n = n0 + tx * 8 + j;
            const int h = n >> 6;       // n / 64
            const int d = n & 63;
            outh[(((size_t)(b * H_ + h) * S_) + s) * D_ + d] = acc[i][j] + bias[n];
        }
    }
}

// ---------------------------------------------------------------------------
// Kernel B: flash-style attention. One block = (b, h, 64-query tile).
// 256 threads, BKV=64 per iteration, online softmax.
// All smem GEMM operands stored reduction-dim-major with stride 65
// (conflict-free in both the micro-GEMMs and the softmax row scans).
// ---------------------------------------------------------------------------
#define PAD 65

__global__ __launch_bounds__(256) void attn_kernel(const float* __restrict__ Q,
                                                   const float* __restrict__ K,
                                                   const float* __restrict__ V,
                                                   const float* __restrict__ mask,
                                                   float* __restrict__ out)
{
    extern __shared__ float sm[];
    float* Qt  = sm;                 // [d][q]  prescaled by 1/sqrt(Dh)
    float* Kt  = Qt + 64 * PAD;      // [d][k]
    float* Vs  = Kt + 64 * PAD;      // [k][d]
    float* St  = Vs + 64 * PAD;      // [k][q]  scores then probs
    float* m_s = St + 64 * PAD;      // [64] running max
    float* l_s = m_s + 64;           // [64] running sum
    float* c_s = l_s + 64;           // [64] correction factor

    const int tid = threadIdx.x;
    const int q0  = blockIdx.x * 64;
    const int h   = blockIdx.y;
    const int b   = blockIdx.z;
    const size_t base = (size_t)(b * H_ + h) * S_ * D_;
    const float scale = 0.125f;      // 1/sqrt(64)

    // Load Q tile transposed + prescaled (coalesced over d)
    #pragma unroll
    for (int i = 0; i < 16; ++i) {
        int e = tid + i * 256;       // 0..4095
        int r = e >> 6, d = e & 63;
        Qt[d * PAD + r] = Q[base + (size_t)(q0 + r) * D_ + d] * scale;
    }
    if (tid < 64) { m_s[tid] = -1e30f; l_s[tid] = 0.f; }

    const int ty = tid >> 4, tx = tid & 15;  // 16x16 for micro-GEMMs
    const int qrow = tid >> 2;               // 4 threads per query row
    const int part = tid & 3;

    float acc[4][4];
    #pragma unroll
    for (int i = 0; i < 4; ++i)
        #pragma unroll
        for (int j = 0; j < 4; ++j) acc[i][j] = 0.f;

    for (int k0 = 0; k0 < S_; k0 += 64) {
        __syncthreads();  // prior-iter readers of Kt/Vs/St done; Qt/m_s/l_s visible on iter 0

        // Load K (transposed) and V tiles, coalesced over d
        #pragma unroll
        for (int i = 0; i < 16; ++i) {
            int e = tid + i * 256;
            int r = e >> 6, d = e & 63;
            Kt[d * PAD + r] = K[base + (size_t)(k0 + r) * D_ + d];
            Vs[r * PAD + d] = V[base + (size_t)(k0 + r) * D_ + d];
        }
        __syncthreads();

        // Scores: s[i][j] for q = ty*4+i, k = tx*4+j
        float s[4][4];
        #pragma unroll
        for (int i = 0; i < 4; ++i)
            #pragma unroll
            for (int j = 0; j < 4; ++j) s[i][j] = 0.f;

        #pragma unroll
        for (int d = 0; d < 64; ++d) {
            float rq[4], rk[4];
            #pragma unroll
            for (int i = 0; i < 4; ++i) rq[i] = Qt[d * PAD + ty * 4 + i];
            #pragma unroll
            for (int j = 0; j < 4; ++j) rk[j] = Kt[d * PAD + tx * 4 + j];
            #pragma unroll
            for (int i = 0; i < 4; ++i)
                #pragma unroll
                for (int j = 0; j < 4; ++j)
                    s[i][j] += rq[i] * rk[j];
        }
        // Write scores transposed [k][q] with additive mask
        #pragma unroll
        for (int j = 0; j < 4; ++j) {
            float mk = mask[b * S_ + k0 + tx * 4 + j];
            #pragma unroll
            for (int i = 0; i < 4; ++i)
                St[(tx * 4 + j) * PAD + ty * 4 + i] = s[i][j] + mk;
        }
        __syncthreads();

        // Online softmax: 4 threads per row scan 16 keys each
        float lmax = -1e30f;
        #pragma unroll
        for (int kk = 0; kk < 16; ++kk)
            lmax = fmaxf(lmax, St[(part * 16 + kk) * PAD + qrow]);
        lmax = fmaxf(lmax, __shfl_xor_sync(0xffffffffu, lmax, 1));
        lmax = fmaxf(lmax, __shfl_xor_sync(0xffffffffu, lmax, 2));

        const float M_old = m_s[qrow];
        const float M_new = fmaxf(M_old, lmax);

        float lsum = 0.f;
        #pragma unroll
        for (int kk = 0; kk < 16; ++kk) {
            int idx = (part * 16 + kk) * PAD + qrow;
            float e = __expf(St[idx] - M_new);
            St[idx] = e;
            lsum += e;
        }
        lsum += __shfl_xor_sync(0xffffffffu, lsum, 1);
        lsum += __shfl_xor_sync(0xffffffffu, lsum, 2);
        if (part == 0) {
            float c = __expf(M_old - M_new);
            l_s[qrow] = l_s[qrow] * c + lsum;
            m_s[qrow] = M_new;
            c_s[qrow] = c;
        }
        __syncthreads();

        // Rescale accumulators, then O += P @ V
        float cf[4];
        #pragma unroll
        for (int i = 0; i < 4; ++i) cf[i] = c_s[ty * 4 + i];
        #pragma unroll
        for (int i = 0; i < 4; ++i)
            #pragma unroll
            for (int j = 0; j < 4; ++j) acc[i][j] *= cf[i];

        #pragma unroll
        for (int k = 0; k < 64; ++k) {
            float rp[4], rv[4];
            #pragma unroll
            for (int i = 0; i < 4; ++i) rp[i] = St[k * PAD + ty * 4 + i];
            #pragma unroll
            for (int j = 0; j < 4; ++j) rv[j] = Vs[k * PAD + tx * 4 + j];
            #pragma unroll
            for (int i = 0; i < 4; ++i)
                #pragma unroll
                for (int j = 0; j < 4; ++j)
                    acc[i][j] += rp[i] * rv[j];
        }
    }
    __syncthreads();

    // Output: [B, S, H*Dh]
    #pragma unroll
    for (int i = 0; i < 4; ++i) {
        const int q = q0 + ty * 4 + i;
        const float inv = 1.f / l_s[ty * 4 + i];
        #pragma unroll
        for (int j = 0; j < 4; ++j) {
            const int d = tx * 4 + j;
            out[((size_t)(b * S_ + q)) * HID + h * D_ + d] = acc[i][j] * inv;
        }
    }
}

// ---------------------------------------------------------------------------
// Launch
// ---------------------------------------------------------------------------
extern "C" void kernel_launch(void* const* d_in, const int* in_sizes, int n_in,
                              void* d_out, int out_size)
{
    const float* X    = (const float*)d_in[0];   // hidden_states [B,S,HID]
    const float* mask = (const float*)d_in[1];   // attention_mask [B,S]
    const float* Wq   = (const float*)d_in[2];
    const float* bq   = (const float*)d_in[3];
    const float* Wk   = (const float*)d_in[4];
    const float* bk   = (const float*)d_in[5];
    const float* Wv   = (const float*)d_in[6];
    const float* bv   = (const float*)d_in[7];
    float* out = (float*)d_out;

    float *dQ, *dK, *dV;
    cudaGetSymbolAddress((void**)&dQ, g_Q);
    cudaGetSymbolAddress((void**)&dK, g_K);
    cudaGetSymbolAddress((void**)&dV, g_V);

    const int attn_smem = (4 * 64 * PAD + 3 * 64) * sizeof(float);  // ~66 KB
    cudaFuncSetAttribute(attn_kernel, cudaFuncAttributeMaxDynamicSharedMemorySize, attn_smem);

    dim3 ggrid(HID / 128, M_ / 128);   // (8, 64)
    qkv_gemm<<<ggrid, 256>>>(X, Wq, bq, dQ);
    qkv_gemm<<<ggrid, 256>>>(X, Wk, bk, dK);
    qkv_gemm<<<ggrid, 256>>>(X, Wv, bv, dV);

    dim3 agrid(S_ / 64, H_, B_);       // (32, 16, 4)
    attn_kernel<<<agrid, 256, attn_smem>>>(dQ, dK, dV, mask, out);
}

// round 2
// speedup vs baseline: 3.6004x; 3.6004x over previous
#include <cuda_runtime.h>
#include <cuda_bf16.h>
#include <cstdint>

#define B_   4
#define S_   2048
#define H_   16
#define D_   64
#define HID  1024
#define M_   (B_ * S_)

__device__ float g_Q[B_ * H_ * S_ * D_];
__device__ float g_K[B_ * H_ * S_ * D_];
__device__ float g_V[B_ * H_ * S_ * D_];

__device__ __forceinline__ uint32_t f2tf(float x) {
    uint32_t r;
    asm("cvt.rna.tf32.f32 %0, %1;" : "=r"(r) : "f"(x));
    return r;
}

#define MMA_TF32(c, a, b)                                              \
    asm volatile(                                                      \
        "mma.sync.aligned.m16n8k8.row.col.f32.tf32.tf32.f32 "          \
        "{%0,%1,%2,%3}, {%4,%5,%6,%7}, {%8,%9}, {%0,%1,%2,%3};\n"      \
        : "+f"((c)[0]), "+f"((c)[1]), "+f"((c)[2]), "+f"((c)[3])       \
        : "r"((a)[0]), "r"((a)[1]), "r"((a)[2]), "r"((a)[3]),          \
          "r"((b)[0]), "r"((b)[1]))

// ---------------------------------------------------------------------------
// Kernel A: tf32 SGEMM  out_head = X @ W + bias -> [B,H,S,Dh] layout.
// 128x128 block, BK=32, 256 threads = 8 warps (2x4), warp tile 64x32.
// ---------------------------------------------------------------------------
#define AS_STRIDE 36   // bank = (4*grp + thr) -> conflict-free A-frag loads
#define BS_STRIDE 136  // bank = (8*thr + grp) -> conflict-free B-frag loads

__global__ __launch_bounds__(256) void qkv_gemm_tf32(const float* __restrict__ X,
                                                     const float* __restrict__ W,
                                                     const float* __restrict__ bias,
                                                     float* __restrict__ outh)
{
    __shared__ uint32_t As[128 * AS_STRIDE];
    __shared__ uint32_t Bs[32 * BS_STRIDE];

    const int tid  = threadIdx.x;
    const int warp = tid >> 5;
    const int lane = tid & 31;
    const int grp  = lane >> 2;
    const int thr  = lane & 3;
    const int wm   = warp >> 2;   // 0..1
    const int wn   = warp & 3;    // 0..3
    const int m0   = blockIdx.y * 128;
    const int n0   = blockIdx.x * 128;

    float acc[4][4][4];
    #pragma unroll
    for (int mt = 0; mt < 4; ++mt)
        #pragma unroll
        for (int nt = 0; nt < 4; ++nt)
            #pragma unroll
            for (int r = 0; r < 4; ++r) acc[mt][nt][r] = 0.f;

    for (int k0 = 0; k0 < HID; k0 += 32) {
        __syncthreads();
        #pragma unroll
        for (int t = 0; t < 4; ++t) {
            int i  = tid + t * 256;
            int ar = i >> 3, ac = (i & 7) * 4;
            float4 av = *reinterpret_cast<const float4*>(&X[(size_t)(m0 + ar) * HID + k0 + ac]);
            As[ar * AS_STRIDE + ac + 0] = f2tf(av.x);
            As[ar * AS_STRIDE + ac + 1] = f2tf(av.y);
            As[ar * AS_STRIDE + ac + 2] = f2tf(av.z);
            As[ar * AS_STRIDE + ac + 3] = f2tf(av.w);
            int br = i >> 5, bc = (i & 31) * 4;
            float4 bv = *reinterpret_cast<const float4*>(&W[(size_t)(k0 + br) * HID + n0 + bc]);
            Bs[br * BS_STRIDE + bc + 0] = f2tf(bv.x);
            Bs[br * BS_STRIDE + bc + 1] = f2tf(bv.y);
            Bs[br * BS_STRIDE + bc + 2] = f2tf(bv.z);
            Bs[br * BS_STRIDE + bc + 3] = f2tf(bv.w);
        }
        __syncthreads();

        #pragma unroll
        for (int kk = 0; kk < 32; kk += 8) {
            uint32_t a[4][4], b[4][2];
            #pragma unroll
            for (int mt = 0; mt < 4; ++mt) {
                int r = wm * 64 + mt * 16 + grp;
                a[mt][0] = As[r * AS_STRIDE + kk + thr];
                a[mt][1] = As[(r + 8) * AS_STRIDE + kk + thr];
                a[mt][2] = As[r * AS_STRIDE + kk + thr + 4];
                a[mt][3] = As[(r + 8) * AS_STRIDE + kk + thr + 4];
            }
            #pragma unroll
            for (int nt = 0; nt < 4; ++nt) {
                int c = wn * 32 + nt * 8 + grp;
                b[nt][0] = Bs[(kk + thr) * BS_STRIDE + c];
                b[nt][1] = Bs[(kk + thr + 4) * BS_STRIDE + c];
            }
            #pragma unroll
            for (int mt = 0; mt < 4; ++mt)
                #pragma unroll
                for (int nt = 0; nt < 4; ++nt)
                    MMA_TF32(acc[mt][nt], a[mt], b[nt]);
        }
    }

    // Epilogue: bias + scatter to [B,H,S,Dh]
    #pragma unroll
    for (int mt = 0; mt < 4; ++mt) {
        #pragma unroll
        for (int nt = 0; nt < 4; ++nt) {
            #pragma unroll
            for (int half = 0; half < 2; ++half) {
                int m = m0 + wm * 64 + mt * 16 + grp + half * 8;
                int b = m >> 11, s = m & 2047;
                #pragma unroll
                for (int j = 0; j < 2; ++j) {
                    int n = n0 + wn * 32 + nt * 8 + 2 * thr + j;
                    int h = n >> 6, d = n & 63;
                    outh[(((size_t)(b * H_ + h) * S_) + s) * D_ + d] =
                        acc[mt][nt][half * 2 + j] + bias[n];
                }
            }
        }
    }
}

// ---------------------------------------------------------------------------
// Kernel B: flash attention with tf32 mma. Block = (b, h, 64-query tile),
// 128 threads = 4 warps, each warp owns 16 query rows. BKV = 64.
// ---------------------------------------------------------------------------
#define QS_STRIDE 68   // A-frag loads: bank = 4*grp + thr
#define KS_STRIDE 68   // B-frag (S mma): bank = 4*grp + thr
#define VS_STRIDE 72   // B-frag (PV mma): bank = 8*thr + grp
#define ST_STRIDE 68

__global__ __launch_bounds__(128) void attn_tf32(const float* __restrict__ Q,
                                                 const float* __restrict__ K,
                                                 const float* __restrict__ V,
                                                 const float* __restrict__ mask,
                                                 float* __restrict__ out)
{
    extern __shared__ uint32_t sm[];
    uint32_t* Qs  = sm;                         // [64][QS_STRIDE] tf32, prescaled
    uint32_t* Ks  = Qs + 64 * QS_STRIDE;        // [64][KS_STRIDE]
    uint32_t* Vs  = Ks + 64 * KS_STRIDE;        // [64][VS_STRIDE]
    uint32_t* St  = Vs + 64 * VS_STRIDE;        // [64][ST_STRIDE] probs tf32
    float*    msk = (float*)(St + 64 * ST_STRIDE);  // [64]

    const int tid  = threadIdx.x;
    const int warp = tid >> 5;
    const int lane = tid & 31;
    const int grp  = lane >> 2;
    const int thr  = lane & 3;
    const int q0   = blockIdx.x * 64;
    const int h    = blockIdx.y;
    const int b    = blockIdx.z;
    const size_t base = (size_t)(b * H_ + h) * S_ * D_;
    const int rw = warp * 16 + grp;   // this thread's first query row (local)

    // Load Q tile, prescale by 1/8 (exact), convert tf32
    #pragma unroll
    for (int t = 0; t < 8; ++t) {
        int i = tid + t * 128;
        int r = i >> 4, c = (i & 15) * 4;
        float4 v = *reinterpret_cast<const float4*>(&Q[base + (size_t)(q0 + r) * D_ + c]);
        Qs[r * QS_STRIDE + c + 0] = f2tf(v.x * 0.125f);
        Qs[r * QS_STRIDE + c + 1] = f2tf(v.y * 0.125f);
        Qs[r * QS_STRIDE + c + 2] = f2tf(v.z * 0.125f);
        Qs[r * QS_STRIDE + c + 3] = f2tf(v.w * 0.125f);
    }

    float mrun[2] = {-1e30f, -1e30f};
    float lrun[2] = {0.f, 0.f};
    float o[8][4];
    #pragma unroll
    for (int nt = 0; nt < 8; ++nt)
        #pragma unroll
        for (int r = 0; r < 4; ++r) o[nt][r] = 0.f;

    for (int k0 = 0; k0 < S_; k0 += 64) {
        __syncthreads();   // prior iter's consumers of Ks/Vs done (also covers Qs on iter 0)
        #pragma unroll
        for (int t = 0; t < 8; ++t) {
            int i = tid + t * 128;
            int r = i >> 4, c = (i & 15) * 4;
            float4 kv = *reinterpret_cast<const float4*>(&K[base + (size_t)(k0 + r) * D_ + c]);
            Ks[r * KS_STRIDE + c + 0] = f2tf(kv.x);
            Ks[r * KS_STRIDE + c + 1] = f2tf(kv.y);
            Ks[r * KS_STRIDE + c + 2] = f2tf(kv.z);
            Ks[r * KS_STRIDE + c + 3] = f2tf(kv.w);
            float4 vv = *reinterpret_cast<const float4*>(&V[base + (size_t)(k0 + r) * D_ + c]);
            Vs[r * VS_STRIDE + c + 0] = f2tf(vv.x);
            Vs[r * VS_STRIDE + c + 1] = f2tf(vv.y);
            Vs[r * VS_STRIDE + c + 2] = f2tf(vv.z);
            Vs[r * VS_STRIDE + c + 3] = f2tf(vv.w);
        }
        if (tid < 64) msk[tid] = mask[b * S_ + k0 + tid];
        __syncthreads();

        // ---- S = Q @ K^T  (contract over d; K[key][d] acts as col-major B) ----
        float s[8][4];
        #pragma unroll
        for (int nt = 0; nt < 8; ++nt)
            #pragma unroll
            for (int r = 0; r < 4; ++r) s[nt][r] = 0.f;

        #pragma unroll
        for (int kk = 0; kk < 64; kk += 8) {
            uint32_t a[4];
            a[0] = Qs[rw * QS_STRIDE + kk + thr];
            a[1] = Qs[(rw + 8) * QS_STRIDE + kk + thr];
            a[2] = Qs[rw * QS_STRIDE + kk + thr + 4];
            a[3] = Qs[(rw + 8) * QS_STRIDE + kk + thr + 4];
            #pragma unroll
            for (int nt = 0; nt < 8; ++nt) {
                uint32_t bb[2];
                int key = nt * 8 + grp;
                bb[0] = Ks[key * KS_STRIDE + kk + thr];
                bb[1] = Ks[key * KS_STRIDE + kk + thr + 4];
                MMA_TF32(s[nt], a, bb);
            }
        }

        // ---- mask + online softmax (rows rw, rw+8; cols 8*nt + 2*thr + {0,1}) ----
        float rmax0 = -1e30f, rmax1 = -1e30f;
        #pragma unroll
        for (int nt = 0; nt < 8; ++nt) {
            int c0 = nt * 8 + 2 * thr;
            s[nt][0] += msk[c0];     s[nt][1] += msk[c0 + 1];
            s[nt][2] += msk[c0];     s[nt][3] += msk[c0 + 1];
            rmax0 = fmaxf(rmax0, fmaxf(s[nt][0], s[nt][1]));
            rmax1 = fmaxf(rmax1, fmaxf(s[nt][2], s[nt][3]));
        }
        rmax0 = fmaxf(rmax0, __shfl_xor_sync(0xffffffffu, rmax0, 1));
        rmax0 = fmaxf(rmax0, __shfl_xor_sync(0xffffffffu, rmax0, 2));
        rmax1 = fmaxf(rmax1, __shfl_xor_sync(0xffffffffu, rmax1, 1));
        rmax1 = fmaxf(rmax1, __shfl_xor_sync(0xffffffffu, rmax1, 2));

        const float mnew0 = fmaxf(mrun[0], rmax0);
        const float mnew1 = fmaxf(mrun[1], rmax1);
        float sum0 = 0.f, sum1 = 0.f;
        #pragma unroll
        for (int nt = 0; nt < 8; ++nt) {
            s[nt][0] = __expf(s[nt][0] - mnew0);
            s[nt][1] = __expf(s[nt][1] - mnew0);
            s[nt][2] = __expf(s[nt][2] - mnew1);
            s[nt][3] = __expf(s[nt][3] - mnew1);
            sum0 += s[nt][0] + s[nt][1];
            sum1 += s[nt][2] + s[nt][3];
        }
        sum0 += __shfl_xor_sync(0xffffffffu, sum0, 1);
        sum0 += __shfl_xor_sync(0xffffffffu, sum0, 2);
        sum1 += __shfl_xor_sync(0xffffffffu, sum1, 1);
        sum1 += __shfl_xor_sync(0xffffffffu, sum1, 2);

        const float c0 = __expf(mrun[0] - mnew0);
        const float c1 = __expf(mrun[1] - mnew1);
        mrun[0] = mnew0;  lrun[0] = lrun[0] * c0 + sum0;
        mrun[1] = mnew1;  lrun[1] = lrun[1] * c1 + sum1;

        #pragma unroll
        for (int nt = 0; nt < 8; ++nt) {
            o[nt][0] *= c0;  o[nt][1] *= c0;
            o[nt][2] *= c1;  o[nt][3] *= c1;
        }

        // ---- stage P (tf32) in smem; rows are warp-private -> __syncwarp only ----
        #pragma unroll
        for (int nt = 0; nt < 8; ++nt) {
            int c = nt * 8 + 2 * thr;
            St[rw * ST_STRIDE + c]           = f2tf(s[nt][0]);
            St[rw * ST_STRIDE + c + 1]       = f2tf(s[nt][1]);
            St[(rw + 8) * ST_STRIDE + c]     = f2tf(s[nt][2]);
            St[(rw + 8) * ST_STRIDE + c + 1] = f2tf(s[nt][3]);
        }
        __syncwarp();

        // ---- O += P @ V  (contract over key; V[key][d] is col-major B) ----
        #pragma unroll
        for (int kk = 0; kk < 64; kk += 8) {
            uint32_t a[4];
            a[0] = St[rw * ST_STRIDE + kk + thr];
            a[1] = St[(rw + 8) * ST_STRIDE + kk + thr];
            a[2] = St[rw * ST_STRIDE + kk + thr + 4];
            a[3] = St[(rw + 8) * ST_STRIDE + kk + thr + 4];
            #pragma unroll
            for (int nt = 0; nt < 8; ++nt) {
                uint32_t bb[2];
                int d = nt * 8 + grp;
                bb[0] = Vs[(kk + thr) * VS_STRIDE + d];
                bb[1] = Vs[(kk + thr + 4) * VS_STRIDE + d];
                MMA_TF32(o[nt], a, bb);
            }
        }
    }

    // Output: [B, S, H*Dh]
    const float inv0 = 1.f / lrun[0];
    const float inv1 = 1.f / lrun[1];
    #pragma unroll
    for (int nt = 0; nt < 8; ++nt) {
        int q  = q0 + rw;
        int d  = nt * 8 + 2 * thr;
        float* p0 = &out[((size_t)(b * S_ + q)) * HID + h * D_ + d];
        p0[0] = o[nt][0] * inv0;
        p0[1] = o[nt][1] * inv0;
        float* p1 = &out[((size_t)(b * S_ + q + 8)) * HID + h * D_ + d];
        p1[0] = o[nt][2] * inv1;
        p1[1] = o[nt][3] * inv1;
    }
}

// ---------------------------------------------------------------------------
// Launch
// ---------------------------------------------------------------------------
extern "C" void kernel_launch(void* const* d_in, const int* in_sizes, int n_in,
                              void* d_out, int out_size)
{
    const float* X    = (const float*)d_in[0];
    const float* mask = (const float*)d_in[1];
    const float* Wq   = (const float*)d_in[2];
    const float* bq   = (const float*)d_in[3];
    const float* Wk   = (const float*)d_in[4];
    const float* bk   = (const float*)d_in[5];
    const float* Wv   = (const float*)d_in[6];
    const float* bv   = (const float*)d_in[7];
    float* out = (float*)d_out;

    float *dQ, *dK, *dV;
    cudaGetSymbolAddress((void**)&dQ, g_Q);
    cudaGetSymbolAddress((void**)&dK, g_K);
    cudaGetSymbolAddress((void**)&dV, g_V);

    const int attn_smem =
        (64 * QS_STRIDE + 64 * KS_STRIDE + 64 * VS_STRIDE + 64 * ST_STRIDE) * 4 + 64 * 4;
    cudaFuncSetAttribute(attn_tf32, cudaFuncAttributeMaxDynamicSharedMemorySize, attn_smem);

    dim3 ggrid(HID / 128, M_ / 128);   // (8, 64)
    qkv_gemm_tf32<<<ggrid, 256>>>(X, Wq, bq, dQ);
    qkv_gemm_tf32<<<ggrid, 256>>>(X, Wk, bk, dK);
    qkv_gemm_tf32<<<ggrid, 256>>>(X, Wv, bv, dV);

    dim3 agrid(S_ / 64, H_, B_);       // (32, 16, 4)
    attn_tf32<<<agrid, 128, attn_smem>>>(dQ, dK, dV, mask, out);
}